// round 3
// baseline (speedup 1.0000x reference)
#include <cuda_runtime.h>
#include <cuda_bf16.h>

#define NN 100000
#define EE 1600000
#define NSEG (NN * 8)           // 800000 segments (dst*8 + rel)
#define NPB 32                  // dst nodes per fused block (100000 = 32*3125 exactly)
#define AST 584                 // A smem row stride (bf16): 576 + 8 pad (4 words mod 32)
#define BST 72                  // B smem row stride (bf16): 64 + 8 pad
#define KW 1152                 // packed W row length: [0,576)=hi, [576,1152)=lo
#define SMEM_F ((2 * NPB * AST + 2 * 64 * BST) * 2)   // 93184 bytes

// ---------------- device scratch ----------------
__device__ __align__(16) unsigned g_cnt[NSEG];
__device__ __align__(16) unsigned g_off[NSEG + 1];
__device__ __align__(16) unsigned g_woff[NSEG];
__device__ __align__(16) unsigned g_bsum[512];
__device__ __align__(16) int      g_sb[EE];
__device__ __align__(16) int      g_ssrc[EE];
__device__ __align__(16) float    g_h[(size_t)NN * 64];
__device__ __align__(16) float    g_h2[(size_t)NN * 64];
__device__ __align__(16) float    g_acc[128];
__device__ __align__(16) float    g_scale[64];
__device__ __align__(16) float    g_shift[64];
__device__ __align__(16) __nv_bfloat16 g_wp1[64 * KW];
__device__ __align__(16) __nv_bfloat16 g_wp2[64 * KW];

// ---------------- prep kernels ----------------
__global__ void zero_kernel(unsigned* cnt, float* acc) {
    int i = blockIdx.x * 256 + threadIdx.x;
    if (i < NSEG) cnt[i] = 0u;
    if (i < 128) acc[i] = 0.f;
}

__global__ void hist_kernel(const int* __restrict__ ei, const int* __restrict__ et,
                            int* __restrict__ sb, unsigned* __restrict__ cnt) {
    int e = blockIdx.x * 256 + threadIdx.x;
    if (e >= EE) return;
    int b = ei[EE + e] * 8 + et[e];
    sb[e] = b;
    atomicAdd(cnt + b, 1u);
}

// 3-pass exclusive scan over 800000 counts (2048 elems / block, 391 blocks)
__global__ void scan1(const unsigned* __restrict__ cnt, unsigned* __restrict__ off,
                      unsigned* __restrict__ bsum) {
    __shared__ unsigned sh[256];
    int t = threadIdx.x;
    int base = blockIdx.x * 2048 + t * 8;
    unsigned v[8], s = 0;
#pragma unroll
    for (int j = 0; j < 8; j++) {
        v[j] = (base + j < NSEG) ? cnt[base + j] : 0u;
        s += v[j];
    }
    sh[t] = s;
    __syncthreads();
    for (int d = 1; d < 256; d <<= 1) {
        unsigned x = (t >= d) ? sh[t - d] : 0u;
        __syncthreads();
        sh[t] += x;
        __syncthreads();
    }
    if (t == 255) bsum[blockIdx.x] = sh[255];
    unsigned run = sh[t] - s;
#pragma unroll
    for (int j = 0; j < 8; j++) {
        if (base + j < NSEG) { off[base + j] = run; run += v[j]; }
    }
}

__global__ void scan2(unsigned* bsum, int nb) {
    __shared__ unsigned sh[512];
    int t = threadIdx.x;
    unsigned v = (t < nb) ? bsum[t] : 0u;
    sh[t] = v;
    __syncthreads();
    for (int d = 1; d < 512; d <<= 1) {
        unsigned x = (t >= d) ? sh[t - d] : 0u;
        __syncthreads();
        sh[t] += x;
        __syncthreads();
    }
    if (t < nb) bsum[t] = sh[t] - v;
}

__global__ void scan3(unsigned* __restrict__ off, unsigned* __restrict__ woff,
                      const unsigned* __restrict__ bsum) {
    int i = blockIdx.x * 256 + threadIdx.x;
    if (i < NSEG) {
        unsigned o = off[i] + bsum[i >> 11];
        off[i] = o;
        woff[i] = o;
    }
    if (i == 0) off[NSEG] = EE;
}

__global__ void sort_kernel(const int* __restrict__ ei, const int* __restrict__ sb,
                            unsigned* __restrict__ woff, int* __restrict__ ssrc) {
    int e = blockIdx.x * 256 + threadIdx.x;
    if (e >= EE) return;
    unsigned pos = atomicAdd(woff + sb[e], 1u);
    ssrc[pos] = ei[e];
}

// pack W[r,d,o] + root[d,o] -> WP[j=o][k]; k in [0,576): hi, [576,1152): lo.
// k' = k % 576: k' < 512 -> W[r=k'>>6][d=k'&63][o], else root[k'-512][o].
__global__ void prep_w(const float* __restrict__ w, const float* __restrict__ root,
                       __nv_bfloat16* __restrict__ wp) {
    int i = blockIdx.x * 256 + threadIdx.x;
    if (i >= 64 * KW) return;
    int j = i / KW, k = i % KW;
    int kk = (k < 576) ? k : k - 576;
    float v;
    if (kk < 512) {
        int r = kk >> 6, d = kk & 63;
        v = w[((size_t)r * 64 + d) * 64 + j];
    } else {
        v = root[(size_t)(kk - 512) * 64 + j];
    }
    __nv_bfloat16 hi = __float2bfloat16(v);
    wp[i] = (k < 576) ? hi : __float2bfloat16(v - __bfloat162float(hi));
}

// ---------------- fused aggregate + GEMM ----------------
__device__ __forceinline__ void cp16(void* dst, const void* src) {
    unsigned s = (unsigned)__cvta_generic_to_shared(dst);
    asm volatile("cp.async.cg.shared.global [%0], [%1], 16;" :: "r"(s), "l"(src));
}

// load one 64x64 bf16 B chunk (8KB): chunk c<9 -> hi cols c*64, c>=9 -> lo cols.
__device__ __forceinline__ void issue_chunk(__nv_bfloat16* bs,
                                            const __nv_bfloat16* wp, int c, int tid) {
    int coloff = (c < 9) ? c * 64 : 576 + (c - 9) * 64;
#pragma unroll
    for (int i = 0; i < 2; i++) {
        int t = tid + i * 256;
        int j = t >> 3, sg = t & 7;
        cp16(bs + j * BST + sg * 8, wp + (size_t)j * KW + coloff + sg * 8);
    }
}

#define MMA16816(c0,c1,c2,c3,a0,a1,a2,a3,b0,b1)                                     \
    asm volatile("mma.sync.aligned.m16n8k16.row.col.f32.bf16.bf16.f32 "             \
                 "{%0,%1,%2,%3},{%4,%5,%6,%7},{%8,%9},{%0,%1,%2,%3};"               \
                 : "+f"(c0), "+f"(c1), "+f"(c2), "+f"(c3)                           \
                 : "r"(a0), "r"(a1), "r"(a2), "r"(a3), "r"(b0), "r"(b1))

__device__ __forceinline__ void store_hilo(__nv_bfloat16* Ah, __nv_bfloat16* Al,
                                           int node, int r, float ax, float ay, int lane) {
    __nv_bfloat162 h, l;
    h.x = __float2bfloat16(ax); h.y = __float2bfloat16(ay);
    l.x = __float2bfloat16(ax - __bfloat162float(h.x));
    l.y = __float2bfloat16(ay - __bfloat162float(h.y));
    ((__nv_bfloat162*)(Ah + node * AST + r * 64))[lane] = h;
    ((__nv_bfloat162*)(Al + node * AST + r * 64))[lane] = l;
}

__global__ void __launch_bounds__(256, 2)
fused_kernel(const float* __restrict__ X, const __nv_bfloat16* __restrict__ WP,
             const float* __restrict__ bias, const unsigned* __restrict__ off,
             const int* __restrict__ ssrc, float* __restrict__ OUT) {
    extern __shared__ char smem[];
    __nv_bfloat16* Ah = (__nv_bfloat16*)smem;          // [NPB][AST]
    __nv_bfloat16* Al = Ah + NPB * AST;                // [NPB][AST]
    __nv_bfloat16* Bs = Al + NPB * AST;                // 2 x [64][BST]

    const int tid = threadIdx.x, wid = tid >> 5, lane = tid & 31;
    const int nbase = blockIdx.x * NPB;

    // prefetch B chunk 0 (overlaps gather phase)
    issue_chunk(Bs, WP, 0, tid);
    asm volatile("cp.async.commit_group;");

    // ---- A root region: cols [512,576) = X rows (hi/lo)
    for (int it = tid; it < NPB * 32; it += 256) {
        int row = it >> 5, dp = it & 31;
        float2 v = *(const float2*)(X + (size_t)(nbase + row) * 64 + dp * 2);
        __nv_bfloat162 h, l;
        h.x = __float2bfloat16(v.x); h.y = __float2bfloat16(v.y);
        l.x = __float2bfloat16(v.x - __bfloat162float(h.x));
        l.y = __float2bfloat16(v.y - __bfloat162float(h.y));
        ((__nv_bfloat162*)(Ah + row * AST + 512))[dp] = h;
        ((__nv_bfloat162*)(Al + row * AST + 512))[dp] = l;
    }

    // ---- segment gather: warp owns 32 CONTIGUOUS segments (4 nodes x 8 rel)
    {
        unsigned segbase = (unsigned)(nbase + wid * 4) * 8;
        unsigned st = off[segbase + lane];
        unsigned en = off[segbase + lane + 1];
        for (int i = 0; i < 32; i += 2) {
            unsigned sa0 = __shfl_sync(0xffffffffu, st, i);
            unsigned ea0 = __shfl_sync(0xffffffffu, en, i);
            unsigned sa1 = __shfl_sync(0xffffffffu, st, i + 1);
            unsigned ea1 = __shfl_sync(0xffffffffu, en, i + 1);
            float ax = 0.f, ay = 0.f, bx = 0.f, by = 0.f;
            unsigned p = sa0, q = sa1;
            while (p < ea0 && q < ea1) {          // interleave 2 segments for MLP
                int s0 = ssrc[p++], s1 = ssrc[q++];
                float2 u = *(const float2*)(X + (size_t)s0 * 64 + lane * 2);
                float2 w = *(const float2*)(X + (size_t)s1 * 64 + lane * 2);
                ax += u.x; ay += u.y; bx += w.x; by += w.y;
            }
            while (p < ea0) {
                int s0 = ssrc[p++];
                float2 u = *(const float2*)(X + (size_t)s0 * 64 + lane * 2);
                ax += u.x; ay += u.y;
            }
            while (q < ea1) {
                int s1 = ssrc[q++];
                float2 w = *(const float2*)(X + (size_t)s1 * 64 + lane * 2);
                bx += w.x; by += w.y;
            }
            float inv0 = 1.0f / fmaxf((float)(ea0 - sa0), 1.0f);
            float inv1 = 1.0f / fmaxf((float)(ea1 - sa1), 1.0f);
            store_hilo(Ah, Al, wid * 4 + (i >> 3), i & 7, ax * inv0, ay * inv0, lane);
            store_hilo(Ah, Al, wid * 4 + ((i + 1) >> 3), (i + 1) & 7, bx * inv1, by * inv1, lane);
        }
    }

    // ---- GEMM: C[32,64] = (Ah+Al)·Bh + Ah·Bl over K=576 (18 chunks of 64)
    const int g = lane >> 2, tig = lane & 3;
    const int warpM = wid & 1, warpN = wid >> 1;
    float c_[2][4];
#pragma unroll
    for (int nt = 0; nt < 2; nt++)
#pragma unroll
        for (int k = 0; k < 4; k++) c_[nt][k] = 0.f;

    for (int c = 0; c < 18; c++) {
        if (c + 1 < 18) {
            issue_chunk(Bs + ((c + 1) & 1) * 64 * BST, WP, c + 1, tid);
            asm volatile("cp.async.commit_group;");
            asm volatile("cp.async.wait_group 1;");
        } else {
            asm volatile("cp.async.wait_group 0;");
        }
        __syncthreads();   // first iter also fences A-fill

        const __nv_bfloat16* Bb = Bs + (c & 1) * 64 * BST + (warpN * 16 + g) * BST;
        const int kbase = (c < 9) ? c * 64 : (c - 9) * 64;
        const int nreg = (c < 9) ? 2 : 1;   // Bh: Ah and Al passes; Bl: Ah only
        for (int rg = 0; rg < nreg; rg++) {
            const __nv_bfloat16* a0p = (rg ? Al : Ah) + (warpM * 16 + g) * AST + kbase;
#pragma unroll
            for (int kt = 0; kt < 4; kt++) {
                int kc = kt * 16 + 2 * tig;
                unsigned a0 = *(const unsigned*)(a0p + kc);
                unsigned a2 = *(const unsigned*)(a0p + kc + 8);
                unsigned a1 = *(const unsigned*)(a0p + kc + 8 * AST);
                unsigned a3 = *(const unsigned*)(a0p + kc + 8 * AST + 8);
#pragma unroll
                for (int nt = 0; nt < 2; nt++) {
                    const __nv_bfloat16* bp = Bb + nt * 8 * BST + kc;
                    unsigned b0 = *(const unsigned*)(bp);
                    unsigned b1 = *(const unsigned*)(bp + 8);
                    MMA16816(c_[nt][0], c_[nt][1], c_[nt][2], c_[nt][3],
                             a0, a1, a2, a3, b0, b1);
                }
            }
        }
        __syncthreads();
    }

    // ---- epilogue: direct store + bias (each (row,col) written once)
    int row = nbase + warpM * 16 + g;
#pragma unroll
    for (int nt = 0; nt < 2; nt++) {
        int col = warpN * 16 + nt * 8 + 2 * tig;
        float2 bb = *(const float2*)(bias + col);
        *(float2*)(OUT + (size_t)row * 64 + col) = make_float2(c_[nt][0] + bb.x, c_[nt][1] + bb.y);
        *(float2*)(OUT + (size_t)(row + 8) * 64 + col) = make_float2(c_[nt][2] + bb.x, c_[nt][3] + bb.y);
    }
}

// ---------------- batch norm ----------------
__global__ void bn_stats(const float* __restrict__ H, float* __restrict__ acc) {
    int ch = threadIdx.x & 63;
    int ry = threadIdx.x >> 6;
    float s = 0.f, q = 0.f;
    for (int r = blockIdx.x * 4 + ry; r < NN; r += gridDim.x * 4) {
        float v = H[(size_t)r * 64 + ch];
        s += v; q += v * v;
    }
    __shared__ float sh[2][4][64];
    sh[0][ry][ch] = s; sh[1][ry][ch] = q;
    __syncthreads();
    if (ry == 0) {
        s = sh[0][0][ch] + sh[0][1][ch] + sh[0][2][ch] + sh[0][3][ch];
        q = sh[1][0][ch] + sh[1][1][ch] + sh[1][2][ch] + sh[1][3][ch];
        atomicAdd(acc + ch, s);
        atomicAdd(acc + 64 + ch, q);
    }
}

__global__ void bn_final(const float* __restrict__ acc,
                         const float* __restrict__ gamma, const float* __restrict__ beta,
                         float* __restrict__ scale, float* __restrict__ shift) {
    int ch = threadIdx.x;
    if (ch >= 64) return;
    const float invN = 1.0f / (float)NN;
    float mu = acc[ch] * invN;
    float var = acc[64 + ch] * invN - mu * mu;
    float sc = gamma[ch] * rsqrtf(var + 1e-5f);
    scale[ch] = sc;
    shift[ch] = beta[ch] - mu * sc;
}

__global__ void bn_apply(const float* __restrict__ H, const float* __restrict__ scale,
                         const float* __restrict__ shift, float* __restrict__ H2) {
    int i = blockIdx.x * 512 + threadIdx.x;
    if (i >= NN * 64) return;
    int ch = i & 63;
    H2[i] = fmaxf(H[i] * scale[ch] + shift[ch], 0.f);
}

// ---------------- launcher ----------------
extern "C" void kernel_launch(void* const* d_in, const int* in_sizes, int n_in,
                              void* d_out, int out_size) {
    const float* x      = (const float*)d_in[0];
    const int*   ei     = (const int*)d_in[1];
    const int*   etype  = (const int*)d_in[2];
    const float* w1     = (const float*)d_in[3];
    const float* root1  = (const float*)d_in[4];
    const float* b1     = (const float*)d_in[5];
    const float* gamma1 = (const float*)d_in[6];
    const float* beta1  = (const float*)d_in[7];
    const float* w2     = (const float*)d_in[8];
    const float* root2  = (const float*)d_in[9];
    const float* b2     = (const float*)d_in[10];
    float* out = (float*)d_out;

    unsigned *cnt, *off, *woff, *bsum;
    int *sb, *ssrc;
    float *h, *h2, *acc, *scale, *shift;
    __nv_bfloat16 *wp1, *wp2;
    cudaGetSymbolAddress((void**)&cnt, g_cnt);
    cudaGetSymbolAddress((void**)&off, g_off);
    cudaGetSymbolAddress((void**)&woff, g_woff);
    cudaGetSymbolAddress((void**)&bsum, g_bsum);
    cudaGetSymbolAddress((void**)&sb, g_sb);
    cudaGetSymbolAddress((void**)&ssrc, g_ssrc);
    cudaGetSymbolAddress((void**)&h, g_h);
    cudaGetSymbolAddress((void**)&h2, g_h2);
    cudaGetSymbolAddress((void**)&acc, g_acc);
    cudaGetSymbolAddress((void**)&scale, g_scale);
    cudaGetSymbolAddress((void**)&shift, g_shift);
    cudaGetSymbolAddress((void**)&wp1, g_wp1);
    cudaGetSymbolAddress((void**)&wp2, g_wp2);

    cudaFuncSetAttribute(fused_kernel, cudaFuncAttributeMaxDynamicSharedMemorySize, SMEM_F);

    const int NB_SCAN1 = (NSEG + 2047) / 2048;   // 391

    zero_kernel<<<(NSEG + 255) / 256, 256>>>(cnt, acc);
    hist_kernel<<<(EE + 255) / 256, 256>>>(ei, etype, sb, cnt);
    scan1<<<NB_SCAN1, 256>>>(cnt, off, bsum);
    scan2<<<1, 512>>>(bsum, NB_SCAN1);
    scan3<<<(NSEG + 255) / 256, 256>>>(off, woff, bsum);
    sort_kernel<<<(EE + 255) / 256, 256>>>(ei, sb, woff, ssrc);
    prep_w<<<(64 * KW + 255) / 256, 256>>>(w1, root1, wp1);
    prep_w<<<(64 * KW + 255) / 256, 256>>>(w2, root2, wp2);

    // layer 1: h = fused(x)
    fused_kernel<<<NN / NPB, 256, SMEM_F>>>(x, wp1, b1, off, ssrc, h);

    // batch norm -> h2 = relu(bn(h))
    bn_stats<<<1024, 256>>>(h, acc);
    bn_final<<<1, 64>>>(acc, gamma1, beta1, scale, shift);
    bn_apply<<<(NN * 64 + 511) / 512, 512>>>(h, scale, shift, h2);

    // layer 2: out = fused(h2)
    fused_kernel<<<NN / NPB, 256, SMEM_F>>>(h2, wp2, b2, off, ssrc, out);
}

// round 4
// speedup vs baseline: 1.1303x; 1.1303x over previous
#include <cuda_runtime.h>
#include <cuda_bf16.h>

#define NN 100000
#define EE 1600000
#define NSEG (NN * 8)           // 800000 segments (dst*8 + rel)
#define NPB 32                  // dst nodes per fused block (100000 = 32*3125 exactly)
#define AST 584                 // A smem row stride (bf16): 576 + 8 pad
#define BST 72                  // B smem row stride (bf16): 64 + 8 pad
#define KW 1152                 // packed W row length: [0,576)=hi, [576,1152)=lo
#define SMEM_F ((2 * NPB * AST + 2 * 64 * BST) * 2)   // 93184 bytes

// ---------------- device scratch ----------------
__device__ __align__(16) unsigned g_cnt[NSEG];
__device__ __align__(16) unsigned g_off[NSEG + 1];
__device__ __align__(16) unsigned g_woff[NSEG];
__device__ __align__(16) unsigned g_bsum[512];
__device__ __align__(16) int      g_sb[EE];
__device__ __align__(16) int      g_ssrc[EE];        // packed: src | (rel<<20)
__device__ __align__(16) float    g_h[(size_t)NN * 64];
__device__ __align__(16) float    g_h2[(size_t)NN * 64];
__device__ __align__(16) float    g_acc[128];
__device__ __align__(16) float    g_scale[64];
__device__ __align__(16) float    g_shift[64];
__device__ __align__(16) __nv_bfloat16 g_wp1[64 * KW];
__device__ __align__(16) __nv_bfloat16 g_wp2[64 * KW];

// ---------------- prep kernels ----------------
__global__ void zero_kernel(unsigned* cnt, float* acc) {
    int i = blockIdx.x * 256 + threadIdx.x;
    if (i < NSEG) cnt[i] = 0u;
    if (i < 128) acc[i] = 0.f;
}

__global__ void hist_kernel(const int* __restrict__ ei, const int* __restrict__ et,
                            int* __restrict__ sb, unsigned* __restrict__ cnt) {
    int e = blockIdx.x * 256 + threadIdx.x;
    if (e >= EE) return;
    int b = ei[EE + e] * 8 + et[e];
    sb[e] = b;
    atomicAdd(cnt + b, 1u);
}

__global__ void scan1(const unsigned* __restrict__ cnt, unsigned* __restrict__ off,
                      unsigned* __restrict__ bsum) {
    __shared__ unsigned sh[256];
    int t = threadIdx.x;
    int base = blockIdx.x * 2048 + t * 8;
    unsigned v[8], s = 0;
#pragma unroll
    for (int j = 0; j < 8; j++) {
        v[j] = (base + j < NSEG) ? cnt[base + j] : 0u;
        s += v[j];
    }
    sh[t] = s;
    __syncthreads();
    for (int d = 1; d < 256; d <<= 1) {
        unsigned x = (t >= d) ? sh[t - d] : 0u;
        __syncthreads();
        sh[t] += x;
        __syncthreads();
    }
    if (t == 255) bsum[blockIdx.x] = sh[255];
    unsigned run = sh[t] - s;
#pragma unroll
    for (int j = 0; j < 8; j++) {
        if (base + j < NSEG) { off[base + j] = run; run += v[j]; }
    }
}

__global__ void scan2(unsigned* bsum, int nb) {
    __shared__ unsigned sh[512];
    int t = threadIdx.x;
    unsigned v = (t < nb) ? bsum[t] : 0u;
    sh[t] = v;
    __syncthreads();
    for (int d = 1; d < 512; d <<= 1) {
        unsigned x = (t >= d) ? sh[t - d] : 0u;
        __syncthreads();
        sh[t] += x;
        __syncthreads();
    }
    if (t < nb) bsum[t] = sh[t] - v;
}

__global__ void scan3(unsigned* __restrict__ off, unsigned* __restrict__ woff,
                      const unsigned* __restrict__ bsum) {
    int i = blockIdx.x * 256 + threadIdx.x;
    if (i < NSEG) {
        unsigned o = off[i] + bsum[i >> 11];
        off[i] = o;
        woff[i] = o;
    }
    if (i == 0) off[NSEG] = EE;
}

__global__ void sort_kernel(const int* __restrict__ ei, const int* __restrict__ sb,
                            unsigned* __restrict__ woff, int* __restrict__ ssrc) {
    int e = blockIdx.x * 256 + threadIdx.x;
    if (e >= EE) return;
    int b = sb[e];
    unsigned pos = atomicAdd(woff + b, 1u);
    ssrc[pos] = ei[e] | ((b & 7) << 20);
}

// pack W[r,d,o] + root[d,o] -> WP[j=o][k]; k in [0,576): hi, [576,1152): lo.
__global__ void prep_w(const float* __restrict__ w, const float* __restrict__ root,
                       __nv_bfloat16* __restrict__ wp) {
    int i = blockIdx.x * 256 + threadIdx.x;
    if (i >= 64 * KW) return;
    int j = i / KW, k = i % KW;
    int kk = (k < 576) ? k : k - 576;
    float v;
    if (kk < 512) {
        int r = kk >> 6, d = kk & 63;
        v = w[((size_t)r * 64 + d) * 64 + j];
    } else {
        v = root[(size_t)(kk - 512) * 64 + j];
    }
    __nv_bfloat16 hi = __float2bfloat16(v);
    wp[i] = (k < 576) ? hi : __float2bfloat16(v - __bfloat162float(hi));
}

// ---------------- fused aggregate + GEMM ----------------
__device__ __forceinline__ void cp16(void* dst, const void* src) {
    unsigned s = (unsigned)__cvta_generic_to_shared(dst);
    asm volatile("cp.async.cg.shared.global [%0], [%1], 16;" :: "r"(s), "l"(src));
}

// one 64x64 bf16 B chunk (8KB): c<9 -> hi cols c*64, c>=9 -> lo cols. 512 threads, 1 cp16 each.
__device__ __forceinline__ void issue_chunk(__nv_bfloat16* bs,
                                            const __nv_bfloat16* wp, int c, int tid) {
    int coloff = (c < 9) ? c * 64 : 576 + (c - 9) * 64;
    int j = tid >> 3, sg = tid & 7;
    cp16(bs + j * BST + sg * 8, wp + (size_t)j * KW + coloff + sg * 8);
}

#define MMA16816(c0,c1,c2,c3,a0,a1,a2,a3,b0,b1)                                     \
    asm volatile("mma.sync.aligned.m16n8k16.row.col.f32.bf16.bf16.f32 "             \
                 "{%0,%1,%2,%3},{%4,%5,%6,%7},{%8,%9},{%0,%1,%2,%3};"               \
                 : "+f"(c0), "+f"(c1), "+f"(c2), "+f"(c3)                           \
                 : "r"(a0), "r"(a1), "r"(a2), "r"(a3), "r"(b0), "r"(b1))

__device__ __forceinline__ void store_hilo(__nv_bfloat16* Ah, __nv_bfloat16* Al,
                                           int node, int r, float ax, float ay, int lane) {
    __nv_bfloat162 h, l;
    h.x = __float2bfloat16(ax); h.y = __float2bfloat16(ay);
    l.x = __float2bfloat16(ax - __bfloat162float(h.x));
    l.y = __float2bfloat16(ay - __bfloat162float(h.y));
    ((__nv_bfloat162*)(Ah + node * AST + r * 64))[lane] = h;
    ((__nv_bfloat162*)(Al + node * AST + r * 64))[lane] = l;
}

__global__ void __launch_bounds__(512, 2)
fused_kernel(const float* __restrict__ X, const __nv_bfloat16* __restrict__ WP,
             const float* __restrict__ bias, const unsigned* __restrict__ off,
             const int* __restrict__ ssrc, float* __restrict__ OUT) {
    extern __shared__ char smem[];
    __nv_bfloat16* Ah = (__nv_bfloat16*)smem;          // [NPB][AST]
    __nv_bfloat16* Al = Ah + NPB * AST;                // [NPB][AST]
    __nv_bfloat16* Bs = Al + NPB * AST;                // 2 x [64][BST]

    const int tid = threadIdx.x, wid = tid >> 5, lane = tid & 31;
    const int nbase = blockIdx.x * NPB;

    // prefetch B chunk 0 (overlaps gather phase)
    issue_chunk(Bs, WP, 0, tid);
    asm volatile("cp.async.commit_group;");

    // ---- A root region: cols [512,576) = X rows (hi/lo)
    for (int it = tid; it < NPB * 32; it += 512) {
        int row = it >> 5, dp = it & 31;
        float2 v = *(const float2*)(X + (size_t)(nbase + row) * 64 + dp * 2);
        __nv_bfloat162 h, l;
        h.x = __float2bfloat16(v.x); h.y = __float2bfloat16(v.y);
        l.x = __float2bfloat16(v.x - __bfloat162float(h.x));
        l.y = __float2bfloat16(v.y - __bfloat162float(h.y));
        ((__nv_bfloat162*)(Ah + row * AST + 512))[dp] = h;
        ((__nv_bfloat162*)(Al + row * AST + 512))[dp] = l;
    }

    // ---- gather: each warp owns 2 nodes; flat 4-edge-unrolled loop, MLP 4,
    //      8-way predicated register accumulation (rel packed in ssrc bits 20-22)
#pragma unroll
    for (int nloc = 0; nloc < 2; nloc++) {
        const int node = nbase + wid * 2 + nloc;
        const unsigned* offp = off + (size_t)node * 8;
        unsigned e0 = offp[0], e8 = offp[8];
        float ax[8], ay[8];
#pragma unroll
        for (int r = 0; r < 8; r++) { ax[r] = 0.f; ay[r] = 0.f; }

        for (unsigned e = e0; e < e8; e += 4) {
            int pk[4];
#pragma unroll
            for (int j = 0; j < 4; j++)
                pk[j] = (e + j < e8) ? ssrc[e + j] : -1;
            float2 v[4];
#pragma unroll
            for (int j = 0; j < 4; j++) {
                v[j] = make_float2(0.f, 0.f);
                if (pk[j] >= 0)
                    v[j] = *(const float2*)(X + (size_t)(pk[j] & 0xFFFFF) * 64 + lane * 2);
            }
#pragma unroll
            for (int j = 0; j < 4; j++) {
                int r = pk[j] >> 20;
#pragma unroll
                for (int rr = 0; rr < 8; rr++)
                    if (r == rr) { ax[rr] += v[j].x; ay[rr] += v[j].y; }
            }
        }
#pragma unroll
        for (int r = 0; r < 8; r++) {
            float inv = 1.0f / fmaxf((float)(offp[r + 1] - offp[r]), 1.0f);
            store_hilo(Ah, Al, wid * 2 + nloc, r, ax[r] * inv, ay[r] * inv, lane);
        }
    }

    // ---- GEMM: C[32,64] = (Ah+Al)·Bh + Ah·Bl over K=576 (18 chunks of 64)
    // 16 warps: warpM in {0,1} (m16), warpN in 0..7 (n8)
    const int g = lane >> 2, tig = lane & 3;
    const int warpM = wid & 1, warpN = wid >> 1;
    float c0 = 0.f, c1 = 0.f, c2 = 0.f, c3 = 0.f;

    for (int c = 0; c < 18; c++) {
        if (c + 1 < 18) {
            issue_chunk(Bs + ((c + 1) & 1) * 64 * BST, WP, c + 1, tid);
            asm volatile("cp.async.commit_group;");
            asm volatile("cp.async.wait_group 1;");
        } else {
            asm volatile("cp.async.wait_group 0;");
        }
        __syncthreads();   // first iter also fences A-fill

        const __nv_bfloat16* Bb = Bs + (c & 1) * 64 * BST + (warpN * 8 + g) * BST;
        const int kbase = (c < 9) ? c * 64 : (c - 9) * 64;
        const int nreg = (c < 9) ? 2 : 1;   // Bh: Ah and Al passes; Bl: Ah only
        for (int rg = 0; rg < nreg; rg++) {
            const __nv_bfloat16* a0p = (rg ? Al : Ah) + (warpM * 16 + g) * AST + kbase;
#pragma unroll
            for (int kt = 0; kt < 4; kt++) {
                int kc = kt * 16 + 2 * tig;
                unsigned a0 = *(const unsigned*)(a0p + kc);
                unsigned a2 = *(const unsigned*)(a0p + kc + 8);
                unsigned a1 = *(const unsigned*)(a0p + kc + 8 * AST);
                unsigned a3 = *(const unsigned*)(a0p + kc + 8 * AST + 8);
                unsigned b0 = *(const unsigned*)(Bb + kc);
                unsigned b1 = *(const unsigned*)(Bb + kc + 8);
                MMA16816(c0, c1, c2, c3, a0, a1, a2, a3, b0, b1);
            }
        }
        __syncthreads();
    }

    // ---- epilogue: direct store + bias
    {
        int row = nbase + warpM * 16 + g;
        int col = warpN * 8 + 2 * tig;
        float2 bb = *(const float2*)(bias + col);
        *(float2*)(OUT + (size_t)row * 64 + col) = make_float2(c0 + bb.x, c1 + bb.y);
        *(float2*)(OUT + (size_t)(row + 8) * 64 + col) = make_float2(c2 + bb.x, c3 + bb.y);
    }
}

// ---------------- batch norm ----------------
__global__ void bn_stats(const float* __restrict__ H, float* __restrict__ acc) {
    int ch = threadIdx.x & 63;
    int ry = threadIdx.x >> 6;
    float s = 0.f, q = 0.f;
    for (int r = blockIdx.x * 4 + ry; r < NN; r += gridDim.x * 4) {
        float v = H[(size_t)r * 64 + ch];
        s += v; q += v * v;
    }
    __shared__ float sh[2][4][64];
    sh[0][ry][ch] = s; sh[1][ry][ch] = q;
    __syncthreads();
    if (ry == 0) {
        s = sh[0][0][ch] + sh[0][1][ch] + sh[0][2][ch] + sh[0][3][ch];
        q = sh[1][0][ch] + sh[1][1][ch] + sh[1][2][ch] + sh[1][3][ch];
        atomicAdd(acc + ch, s);
        atomicAdd(acc + 64 + ch, q);
    }
}

__global__ void bn_final(const float* __restrict__ acc,
                         const float* __restrict__ gamma, const float* __restrict__ beta,
                         float* __restrict__ scale, float* __restrict__ shift) {
    int ch = threadIdx.x;
    if (ch >= 64) return;
    const float invN = 1.0f / (float)NN;
    float mu = acc[ch] * invN;
    float var = acc[64 + ch] * invN - mu * mu;
    float sc = gamma[ch] * rsqrtf(var + 1e-5f);
    scale[ch] = sc;
    shift[ch] = beta[ch] - mu * sc;
}

__global__ void bn_apply(const float* __restrict__ H, const float* __restrict__ scale,
                         const float* __restrict__ shift, float* __restrict__ H2) {
    int i = blockIdx.x * 512 + threadIdx.x;
    if (i >= NN * 64) return;
    int ch = i & 63;
    H2[i] = fmaxf(H[i] * scale[ch] + shift[ch], 0.f);
}

// ---------------- launcher ----------------
extern "C" void kernel_launch(void* const* d_in, const int* in_sizes, int n_in,
                              void* d_out, int out_size) {
    const float* x      = (const float*)d_in[0];
    const int*   ei     = (const int*)d_in[1];
    const int*   etype  = (const int*)d_in[2];
    const float* w1     = (const float*)d_in[3];
    const float* root1  = (const float*)d_in[4];
    const float* b1     = (const float*)d_in[5];
    const float* gamma1 = (const float*)d_in[6];
    const float* beta1  = (const float*)d_in[7];
    const float* w2     = (const float*)d_in[8];
    const float* root2  = (const float*)d_in[9];
    const float* b2     = (const float*)d_in[10];
    float* out = (float*)d_out;

    unsigned *cnt, *off, *woff, *bsum;
    int *sb, *ssrc;
    float *h, *h2, *acc, *scale, *shift;
    __nv_bfloat16 *wp1, *wp2;
    cudaGetSymbolAddress((void**)&cnt, g_cnt);
    cudaGetSymbolAddress((void**)&off, g_off);
    cudaGetSymbolAddress((void**)&woff, g_woff);
    cudaGetSymbolAddress((void**)&bsum, g_bsum);
    cudaGetSymbolAddress((void**)&sb, g_sb);
    cudaGetSymbolAddress((void**)&ssrc, g_ssrc);
    cudaGetSymbolAddress((void**)&h, g_h);
    cudaGetSymbolAddress((void**)&h2, g_h2);
    cudaGetSymbolAddress((void**)&acc, g_acc);
    cudaGetSymbolAddress((void**)&scale, g_scale);
    cudaGetSymbolAddress((void**)&shift, g_shift);
    cudaGetSymbolAddress((void**)&wp1, g_wp1);
    cudaGetSymbolAddress((void**)&wp2, g_wp2);

    cudaFuncSetAttribute(fused_kernel, cudaFuncAttributeMaxDynamicSharedMemorySize, SMEM_F);

    const int NB_SCAN1 = (NSEG + 2047) / 2048;   // 391

    zero_kernel<<<(NSEG + 255) / 256, 256>>>(cnt, acc);
    hist_kernel<<<(EE + 255) / 256, 256>>>(ei, etype, sb, cnt);
    scan1<<<NB_SCAN1, 256>>>(cnt, off, bsum);
    scan2<<<1, 512>>>(bsum, NB_SCAN1);
    scan3<<<(NSEG + 255) / 256, 256>>>(off, woff, bsum);
    sort_kernel<<<(EE + 255) / 256, 256>>>(ei, sb, woff, ssrc);
    prep_w<<<(64 * KW + 255) / 256, 256>>>(w1, root1, wp1);
    prep_w<<<(64 * KW + 255) / 256, 256>>>(w2, root2, wp2);

    // layer 1: h = fused(x)
    fused_kernel<<<NN / NPB, 512, SMEM_F>>>(x, wp1, b1, off, ssrc, h);

    // batch norm -> h2 = relu(bn(h))
    bn_stats<<<1024, 256>>>(h, acc);
    bn_final<<<1, 64>>>(acc, gamma1, beta1, scale, shift);
    bn_apply<<<(NN * 64 + 511) / 512, 512>>>(h, scale, shift, h2);

    // layer 2: out = fused(h2)
    fused_kernel<<<NN / NPB, 512, SMEM_F>>>(h2, wp2, b2, off, ssrc, out);
}